// round 14
// baseline (speedup 1.0000x reference)
#include <cuda_runtime.h>
#include <cstdint>

#define DD 1024
#define MM 512
#define CC 256
#define BB 8192

#define NEWTON_ITERS 10

// ---------------- scratch (device globals: allocation-free) ----------------
__device__ float g_state_p[(size_t)DD * BB];
__device__ float g_T1[DD * DD];
__device__ float g_cov_p[DD * DD];
__device__ float g_HP[MM * DD];
__device__ float g_S[MM * MM];
__device__ float g_PHt[DD * MM];
__device__ float g_Ya[MM * MM];
__device__ float g_Yb[MM * MM];
__device__ float g_Ka[DD * MM];
__device__ float g_Kb[DD * MM];
__device__ float g_innov[(size_t)MM * BB];

__device__ unsigned g_ninf_bits;

// ---------------- tf32 helpers ----------------
__device__ __forceinline__ uint2 split_tf32(float x)
{
    uint32_t h, l;
    asm("cvt.rna.tf32.f32 %0, %1;" : "=r"(h) : "f"(x));
    float hf = __uint_as_float(h);
    float r = x - hf;
    asm("cvt.rna.tf32.f32 %0, %1;" : "=r"(l) : "f"(r));
    return make_uint2(h, l);
}

__device__ __forceinline__ void mma_tf32(float* d, const uint32_t* a, const uint32_t* b)
{
    asm volatile(
        "mma.sync.aligned.m16n8k8.row.col.f32.tf32.tf32.f32 "
        "{%0,%1,%2,%3}, {%4,%5,%6,%7}, {%8,%9}, {%0,%1,%2,%3};"
        : "+f"(d[0]), "+f"(d[1]), "+f"(d[2]), "+f"(d[3])
        : "r"(a[0]), "r"(a[1]), "r"(a[2]), "r"(a[3]), "r"(b[0]), "r"(b[1]));
}

// ---------------- double-buffered GEMM tile body ----------------
// C[M,N] = alpha * (A[M,K] @ op(B)) + beta * E[M,N]; op(B)=B (TB=0) or B^T (TB=1).
// Row-major. E may be nullptr or alias C.
// Smem holds (tf32_hi, tf32_lo) interleaved as uint2 -> one LDS.64 per operand
// element feeds all three mma passes. Row stride LD = dim+4 (uint2 units),
// LD % 16 == 4 -> fragment LDS.64 is bank-conflict-free per 16-lane phase.
template <int BM, int BN, int BK, int WM, int WN, bool TB>
__device__ __forceinline__ void gemm_tile(
    uint2* __restrict__ As, uint2* __restrict__ Bs,
    const float* __restrict__ A, const float* __restrict__ B,
    const float* E, float* C,
    int M, int N, int K, float alpha, float beta, int bm, int bn)
{
    constexpr int NW_M = BM / WM;
    constexpr int NW_N = BN / WN;
    constexpr int THREADS = NW_M * NW_N * 32;
    constexpr int MI = WM / 16;
    constexpr int NI = WN / 8;
    constexpr int KSTEPS = BK / 8;
    constexpr int A_LD = (BM * BK) / (THREADS * 4);
    constexpr int B_LD = (BN * BK) / (THREADS * 4);
    constexpr int LDA = BM + 4;     // uint2 units; % 16 == 4
    constexpr int LDB = BN + 4;
    constexpr int ABUF = BK * LDA;
    constexpr int BBUF = BK * LDB;

    const int tid = threadIdx.x;
    const int lane = tid & 31;
    const int warp = tid >> 5;
    const int wm = (warp / NW_N) * WM;
    const int wn = (warp % NW_N) * WN;
    const int gr = lane >> 2;
    const int gc = lane & 3;

    float acc[MI][NI][4];
#pragma unroll
    for (int i = 0; i < MI; ++i)
#pragma unroll
        for (int j = 0; j < NI; ++j)
#pragma unroll
            for (int q = 0; q < 4; ++q) acc[i][j][q] = 0.0f;

    float4 a_st[A_LD], b_st[B_LD];

    auto load_tiles = [&](int k0) {
#pragma unroll
        for (int li = 0; li < A_LD; ++li) {
            int idx = tid + li * THREADS;
            int row = idx / (BK / 4);
            int kc = (idx % (BK / 4)) * 4;
            a_st[li] = *reinterpret_cast<const float4*>(
                &A[(size_t)(bm + row) * K + k0 + kc]);
        }
        if constexpr (!TB) {
#pragma unroll
            for (int li = 0; li < B_LD; ++li) {
                int idx = tid + li * THREADS;
                int kr = idx / (BN / 4);
                int nc = (idx % (BN / 4)) * 4;
                b_st[li] = *reinterpret_cast<const float4*>(
                    &B[(size_t)(k0 + kr) * N + bn + nc]);
            }
        } else {
#pragma unroll
            for (int li = 0; li < B_LD; ++li) {
                int idx = tid + li * THREADS;
                int nrow = idx / (BK / 4);
                int kc = (idx % (BK / 4)) * 4;
                b_st[li] = *reinterpret_cast<const float4*>(
                    &B[(size_t)(bn + nrow) * K + k0 + kc]);
            }
        }
    };

    auto store_tiles = [&](int buf) {
        uint2* aS = As + buf * ABUF;
        uint2* bS = Bs + buf * BBUF;
#pragma unroll
        for (int li = 0; li < A_LD; ++li) {
            int idx = tid + li * THREADS;
            int row = idx / (BK / 4);
            int kc = (idx % (BK / 4)) * 4;
            const float* v = reinterpret_cast<const float*>(&a_st[li]);
#pragma unroll
            for (int j = 0; j < 4; ++j)
                aS[(kc + j) * LDA + row] = split_tf32(v[j]);
        }
        if constexpr (!TB) {
#pragma unroll
            for (int li = 0; li < B_LD; ++li) {
                int idx = tid + li * THREADS;
                int kr = idx / (BN / 4);
                int nc = (idx % (BN / 4)) * 4;
                const float* v = reinterpret_cast<const float*>(&b_st[li]);
#pragma unroll
                for (int j = 0; j < 4; ++j)
                    bS[kr * LDB + nc + j] = split_tf32(v[j]);
            }
        } else {
#pragma unroll
            for (int li = 0; li < B_LD; ++li) {
                int idx = tid + li * THREADS;
                int nrow = idx / (BK / 4);
                int kc = (idx % (BK / 4)) * 4;
                const float* v = reinterpret_cast<const float*>(&b_st[li]);
#pragma unroll
                for (int j = 0; j < 4; ++j)
                    bS[(kc + j) * LDB + nrow] = split_tf32(v[j]);
            }
        }
    };

    const int ntiles = K / BK;

    load_tiles(0);
    store_tiles(0);
    __syncthreads();

    for (int t = 0; t < ntiles; ++t) {
        const int cur = t & 1;
        const bool has_next = (t + 1) < ntiles;

        if (has_next) load_tiles((t + 1) * BK);

        const uint2* aS = As + cur * ABUF;
        const uint2* bS = Bs + cur * BBUF;
#pragma unroll
        for (int ks = 0; ks < KSTEPS; ++ks) {
            uint32_t ahi[MI][4], alo[MI][4];
#pragma unroll
            for (int mi = 0; mi < MI; ++mi) {
                int r0 = wm + mi * 16 + gr;
                int c0 = ks * 8 + gc;
                uint2 v0 = aS[c0 * LDA + r0];
                uint2 v1 = aS[c0 * LDA + r0 + 8];
                uint2 v2 = aS[(c0 + 4) * LDA + r0];
                uint2 v3 = aS[(c0 + 4) * LDA + r0 + 8];
                ahi[mi][0] = v0.x; alo[mi][0] = v0.y;
                ahi[mi][1] = v1.x; alo[mi][1] = v1.y;
                ahi[mi][2] = v2.x; alo[mi][2] = v2.y;
                ahi[mi][3] = v3.x; alo[mi][3] = v3.y;
            }
            uint32_t bhi[NI][2], blo[NI][2];
#pragma unroll
            for (int ni = 0; ni < NI; ++ni) {
                int n0 = wn + ni * 8 + gr;
                int kr = ks * 8 + gc;
                uint2 v0 = bS[kr * LDB + n0];
                uint2 v1 = bS[(kr + 4) * LDB + n0];
                bhi[ni][0] = v0.x; blo[ni][0] = v0.y;
                bhi[ni][1] = v1.x; blo[ni][1] = v1.y;
            }
#pragma unroll
            for (int mi = 0; mi < MI; ++mi)
#pragma unroll
                for (int ni = 0; ni < NI; ++ni) mma_tf32(acc[mi][ni], ahi[mi], bhi[ni]);
#pragma unroll
            for (int mi = 0; mi < MI; ++mi)
#pragma unroll
                for (int ni = 0; ni < NI; ++ni) mma_tf32(acc[mi][ni], ahi[mi], blo[ni]);
#pragma unroll
            for (int mi = 0; mi < MI; ++mi)
#pragma unroll
                for (int ni = 0; ni < NI; ++ni) mma_tf32(acc[mi][ni], alo[mi], bhi[ni]);
        }

        if (has_next) {
            store_tiles(1 - cur);
            __syncthreads();
        }
    }

#pragma unroll
    for (int mi = 0; mi < MI; ++mi) {
        int r0 = bm + wm + mi * 16 + gr;
#pragma unroll
        for (int ni = 0; ni < NI; ++ni) {
            int c = bn + wn + ni * 8 + gc * 2;
            float2 v0 = make_float2(alpha * acc[mi][ni][0], alpha * acc[mi][ni][1]);
            float2 v1 = make_float2(alpha * acc[mi][ni][2], alpha * acc[mi][ni][3]);
            if (E != nullptr) {
                float2 e0 = *reinterpret_cast<const float2*>(&E[(size_t)r0 * N + c]);
                float2 e1 = *reinterpret_cast<const float2*>(&E[(size_t)(r0 + 8) * N + c]);
                v0.x += beta * e0.x; v0.y += beta * e0.y;
                v1.x += beta * e1.x; v1.y += beta * e1.y;
            }
            *reinterpret_cast<float2*>(&C[(size_t)r0 * N + c]) = v0;
            *reinterpret_cast<float2*>(&C[(size_t)(r0 + 8) * N + c]) = v1;
        }
    }
}

// ---------------- kernels ----------------
template <int BM, int BN, int BK, int WM, int WN, bool TB>
__global__ void __launch_bounds__((BM / WM) * (BN / WN) * 32)
gemm_tc_k(const float* __restrict__ A, const float* __restrict__ B,
          const float* E, float* C, int M, int N, int K, float alpha, float beta)
{
    __shared__ uint2 As[2 * BK * (BM + 4)];
    __shared__ uint2 Bs[2 * BK * (BN + 4)];
    gemm_tile<BM, BN, BK, WM, WN, TB>(As, Bs, A, B, E, C,
                                      M, N, K, alpha, beta,
                                      blockIdx.y * BM, blockIdx.x * BN);
}

// Two independent GEMMs fused by grid partition; per-job transpose flags.
template <int BM, int BN, int BK, int WM, int WN, bool TB0, bool TB1>
__global__ void __launch_bounds__((BM / WM) * (BN / WN) * 32)
gemm_pair_k(const float* A0, const float* B0, const float* E0, float* C0,
            int M0, int N0, int K0, float al0, float be0, int gx0, int nb0,
            const float* A1, const float* B1, const float* E1, float* C1,
            int M1, int N1, int K1, float al1, float be1, int gx1)
{
    __shared__ uint2 As[2 * BK * (BM + 4)];
    __shared__ uint2 Bs[2 * BK * (BN + 4)];
    int b = blockIdx.x;
    if (b < nb0) {
        gemm_tile<BM, BN, BK, WM, WN, TB0>(As, Bs, A0, B0, E0, C0,
                                           M0, N0, K0, al0, be0,
                                           (b / gx0) * BM, (b % gx0) * BN);
    } else {
        b -= nb0;
        gemm_tile<BM, BN, BK, WM, WN, TB1>(As, Bs, A1, B1, E1, C1,
                                           M1, N1, K1, al1, be1,
                                           (b / gx1) * BM, (b % gx1) * BN);
    }
}

// ---------------- Newton-Schulz setup kernels ----------------
__global__ void reset_norm_k() { g_ninf_bits = 0u; }

__global__ void rowsum_k(const float* __restrict__ S)
{
    __shared__ float sh[256];
    int r = blockIdx.x;
    float s = 0.0f;
    for (int c = threadIdx.x; c < MM; c += 256) s += fabsf(S[(size_t)r * MM + c]);
    sh[threadIdx.x] = s;
    __syncthreads();
    for (int o = 128; o > 0; o >>= 1) {
        if (threadIdx.x < o) sh[threadIdx.x] += sh[threadIdx.x + o];
        __syncthreads();
    }
    if (threadIdx.x == 0) atomicMax(&g_ninf_bits, __float_as_uint(sh[0]));
}

// Y0 = c*S (MM*MM), G0 = c*PHt (DD*MM), c = 1/ninf   (X0 = c*I)
__global__ void scale_init_k(const float* __restrict__ S, const float* __restrict__ PHt,
                             float* __restrict__ Y0, float* __restrict__ G0)
{
    float c = 1.0f / __uint_as_float(g_ninf_bits);
    int idx = blockIdx.x * blockDim.x + threadIdx.x;
    if (idx < MM * MM) Y0[idx] = c * S[idx];
    int idx2 = idx - MM * MM;
    if (idx2 >= 0 && idx2 < DD * MM) G0[idx2] = c * PHt[idx2];
}

// ---------------- host helpers (stream-aware) ----------------
template <bool TB>
static void gemm_big(cudaStream_t st, const float* A, const float* B, const float* E,
                     float* C, int M, int N, int K, float alpha, float beta)
{
    dim3 grid(N / 128, M / 128);
    gemm_tc_k<128, 128, 16, 32, 64, TB><<<grid, 256, 0, st>>>(A, B, E, C, M, N, K, alpha, beta);
}

template <bool TB>
static void gemm_mid(cudaStream_t st, const float* A, const float* B, const float* E,
                     float* C, int M, int N, int K, float alpha, float beta)
{
    dim3 grid(N / 64, M / 64);
    gemm_tc_k<64, 64, 16, 32, 32, TB><<<grid, 128, 0, st>>>(A, B, E, C, M, N, K, alpha, beta);
}

template <bool TB0, bool TB1>
static void gemm_pair(cudaStream_t st,
                      const float* A0, const float* B0, const float* E0, float* C0,
                      int M0, int N0, int K0, float al0, float be0,
                      const float* A1, const float* B1, const float* E1, float* C1,
                      int M1, int N1, int K1, float al1, float be1)
{
    int gx0 = N0 / 64, nb0 = gx0 * (M0 / 64);
    int gx1 = N1 / 64, nb1 = gx1 * (M1 / 64);
    gemm_pair_k<64, 64, 16, 32, 32, TB0, TB1><<<nb0 + nb1, 128, 0, st>>>(
        A0, B0, E0, C0, M0, N0, K0, al0, be0, gx0, nb0,
        A1, B1, E1, C1, M1, N1, K1, al1, be1, gx1);
}

extern "C" void kernel_launch(void* const* d_in, const int* in_sizes, int n_in,
                              void* d_out, int out_size)
{
    (void)in_sizes; (void)n_in; (void)out_size;

    const float* state     = (const float*)d_in[0];
    const float* state_cov = (const float*)d_in[1];
    const float* meas      = (const float*)d_in[2];
    const float* control   = (const float*)d_in[3];
    const float* F         = (const float*)d_in[4];
    const float* Q         = (const float*)d_in[5];
    const float* Bc        = (const float*)d_in[6];
    const float* H         = (const float*)d_in[7];
    const float* R         = (const float*)d_in[8];

    float *state_p, *T1, *cov_p, *HP, *S, *PHt, *Ya, *Yb, *Ka, *Kb, *innov;
    cudaGetSymbolAddress((void**)&state_p, g_state_p);
    cudaGetSymbolAddress((void**)&T1, g_T1);
    cudaGetSymbolAddress((void**)&cov_p, g_cov_p);
    cudaGetSymbolAddress((void**)&HP, g_HP);
    cudaGetSymbolAddress((void**)&S, g_S);
    cudaGetSymbolAddress((void**)&PHt, g_PHt);
    cudaGetSymbolAddress((void**)&Ya, g_Ya);
    cudaGetSymbolAddress((void**)&Yb, g_Yb);
    cudaGetSymbolAddress((void**)&Ka, g_Ka);
    cudaGetSymbolAddress((void**)&Kb, g_Kb);
    cudaGetSymbolAddress((void**)&innov, g_innov);

    float* out_state = (float*)d_out;                 // [D, B]
    float* out_cov   = out_state + (size_t)DD * BB;   // [D, D]

    // one-time side-stream + events (resource init only; no work is skipped)
    static cudaStream_t s2 = nullptr;
    static cudaEvent_t ev_fork = nullptr, ev_g = nullptr, ev_done = nullptr;
    if (s2 == nullptr) {
        cudaStreamCreateWithFlags(&s2, cudaStreamNonBlocking);
        cudaEventCreateWithFlags(&ev_fork, cudaEventDisableTiming);
        cudaEventCreateWithFlags(&ev_g, cudaEventDisableTiming);
        cudaEventCreateWithFlags(&ev_done, cudaEventDisableTiming);
    }
    cudaStream_t s0 = (cudaStream_t)0;

    // ---- fork ----
    cudaEventRecord(ev_fork, s0);
    cudaStreamWaitEvent(s2, ev_fork, 0);

    // ===== stream s2: state chain (big batch GEMMs) =====
    gemm_big<false>(s2, F, state, nullptr, state_p, DD, BB, DD, 1.0f, 0.0f);
    gemm_big<false>(s2, Bc, control, state_p, state_p, DD, BB, CC, 1.0f, 1.0f);
    gemm_big<false>(s2, H, state_p, meas, innov, MM, BB, DD, -1.0f, 1.0f);

    // ===== stream 0: covariance chain =====
    gemm_mid<false>(s0, F, state_cov, nullptr, T1, DD, DD, DD, 1.0f, 0.0f);
    gemm_mid<true >(s0, T1, F, Q, cov_p, DD, DD, DD, 1.0f, 1.0f);
    gemm_pair<false, true>(s0,
        H,     cov_p, nullptr, HP,  MM, DD, DD, 1.0f, 0.0f,
        cov_p, H,     nullptr, PHt, DD, MM, DD, 1.0f, 0.0f);
    gemm_mid<true>(s0, HP, H, R, S, MM, MM, DD, 1.0f, 1.0f);

    // Newton-Schulz with X0 = I/||S||inf: Y0=c*S, G0=c*PHt
    reset_norm_k<<<1, 1, 0, s0>>>();
    rowsum_k<<<MM, 256, 0, s0>>>(S);
    scale_init_k<<<(MM * MM + DD * MM + 255) / 256, 256, 0, s0>>>(S, PHt, Ya, Ka);

    float* Y = Ya; float* Yn = Yb;
    float* G = Ka; float* Gn = Kb;
    for (int it = 0; it < NEWTON_ITERS; ++it) {
        gemm_pair<false, false>(s0,
            Y, Y, Y, Yn, MM, MM, MM, -1.0f, 2.0f,
            G, Y, G, Gn, DD, MM, MM, -1.0f, 2.0f);
        float* t = Y; Y = Yn; Yn = t;
        t = G; G = Gn; Gn = t;
    }
    // G == Kalman gain
    cudaEventRecord(ev_g, s0);

    // out_cov on stream 0 (needs G, HP, cov_p)
    gemm_mid<false>(s0, G, HP, cov_p, out_cov, DD, DD, MM, -1.0f, 1.0f);

    // out_state on s2 (needs G from stream 0, innov/state_p from s2)
    cudaStreamWaitEvent(s2, ev_g, 0);
    gemm_big<false>(s2, G, innov, state_p, out_state, DD, BB, MM, 1.0f, 1.0f);

    // ---- join ----
    cudaEventRecord(ev_done, s2);
    cudaStreamWaitEvent(s0, ev_done, 0);
}

// round 15
// speedup vs baseline: 1.2707x; 1.2707x over previous
#include <cuda_runtime.h>
#include <cstdint>

#define DD 1024
#define MM 512
#define CC 256
#define BB 8192

#define NEWTON_ITERS 10

// ---------------- scratch (device globals: allocation-free) ----------------
__device__ float g_state_p[(size_t)DD * BB];
__device__ float g_T1[DD * DD];
__device__ float g_cov_p[DD * DD];
__device__ float g_HP[MM * DD];
__device__ float g_S[MM * MM];
__device__ float g_PHt[DD * MM];
__device__ float g_Ya[MM * MM];
__device__ float g_Yb[MM * MM];
__device__ float g_Xa[MM * MM];
__device__ float g_Xb[MM * MM];
__device__ float g_K[DD * MM];
__device__ float g_innov[(size_t)MM * BB];

__device__ unsigned g_ninf_bits;

// ---------------- tf32 helpers ----------------
__device__ __forceinline__ void split_tf32(float x, uint32_t& h, uint32_t& l)
{
    asm("cvt.rna.tf32.f32 %0, %1;" : "=r"(h) : "f"(x));
    float hf = __uint_as_float(h);
    float r = x - hf;
    asm("cvt.rna.tf32.f32 %0, %1;" : "=r"(l) : "f"(r));
}

__device__ __forceinline__ void mma_tf32(float* d, const uint32_t* a, const uint32_t* b)
{
    asm volatile(
        "mma.sync.aligned.m16n8k8.row.col.f32.tf32.tf32.f32 "
        "{%0,%1,%2,%3}, {%4,%5,%6,%7}, {%8,%9}, {%0,%1,%2,%3};"
        : "+f"(d[0]), "+f"(d[1]), "+f"(d[2]), "+f"(d[3])
        : "r"(a[0]), "r"(a[1]), "r"(a[2]), "r"(a[3]), "r"(b[0]), "r"(b[1]));
}

// ---------------- double-buffered GEMM tile body (R11 core, unchanged) ----------------
template <int BM, int BN, int BK, int WM, int WN, bool TB>
__device__ __forceinline__ void gemm_tile(
    uint32_t* __restrict__ AsH, uint32_t* __restrict__ AsL,
    uint32_t* __restrict__ BsH, uint32_t* __restrict__ BsL,
    const float* __restrict__ A, const float* __restrict__ B,
    const float* E, float* C,
    int M, int N, int K, float alpha, float beta, int bm, int bn)
{
    constexpr int NW_M = BM / WM;
    constexpr int NW_N = BN / WN;
    constexpr int THREADS = NW_M * NW_N * 32;
    constexpr int MI = WM / 16;
    constexpr int NI = WN / 8;
    constexpr int KSTEPS = BK / 8;
    constexpr int A_LD = (BM * BK) / (THREADS * 4);
    constexpr int B_LD = (BN * BK) / (THREADS * 4);
    constexpr int LDA = BM + 8;
    constexpr int LDB = BN + 8;
    constexpr int ABUF = BK * LDA;
    constexpr int BBUF = BK * LDB;

    const int tid = threadIdx.x;
    const int lane = tid & 31;
    const int warp = tid >> 5;
    const int wm = (warp / NW_N) * WM;
    const int wn = (warp % NW_N) * WN;
    const int gr = lane >> 2;
    const int gc = lane & 3;

    float acc[MI][NI][4];
#pragma unroll
    for (int i = 0; i < MI; ++i)
#pragma unroll
        for (int j = 0; j < NI; ++j)
#pragma unroll
            for (int q = 0; q < 4; ++q) acc[i][j][q] = 0.0f;

    float4 a_st[A_LD], b_st[B_LD];

    auto load_tiles = [&](int k0) {
#pragma unroll
        for (int li = 0; li < A_LD; ++li) {
            int idx = tid + li * THREADS;
            int row = idx / (BK / 4);
            int kc = (idx % (BK / 4)) * 4;
            a_st[li] = *reinterpret_cast<const float4*>(
                &A[(size_t)(bm + row) * K + k0 + kc]);
        }
        if constexpr (!TB) {
#pragma unroll
            for (int li = 0; li < B_LD; ++li) {
                int idx = tid + li * THREADS;
                int kr = idx / (BN / 4);
                int nc = (idx % (BN / 4)) * 4;
                b_st[li] = *reinterpret_cast<const float4*>(
                    &B[(size_t)(k0 + kr) * N + bn + nc]);
            }
        } else {
#pragma unroll
            for (int li = 0; li < B_LD; ++li) {
                int idx = tid + li * THREADS;
                int nrow = idx / (BK / 4);
                int kc = (idx % (BK / 4)) * 4;
                b_st[li] = *reinterpret_cast<const float4*>(
                    &B[(size_t)(bn + nrow) * K + k0 + kc]);
            }
        }
    };

    auto store_tiles = [&](int buf) {
        uint32_t* aH = AsH + buf * ABUF;
        uint32_t* aL = AsL + buf * ABUF;
        uint32_t* bH = BsH + buf * BBUF;
        uint32_t* bL = BsL + buf * BBUF;
#pragma unroll
        for (int li = 0; li < A_LD; ++li) {
            int idx = tid + li * THREADS;
            int row = idx / (BK / 4);
            int kc = (idx % (BK / 4)) * 4;
            const float* v = reinterpret_cast<const float*>(&a_st[li]);
#pragma unroll
            for (int j = 0; j < 4; ++j) {
                uint32_t h, l;
                split_tf32(v[j], h, l);
                aH[(kc + j) * LDA + row] = h;
                aL[(kc + j) * LDA + row] = l;
            }
        }
        if constexpr (!TB) {
#pragma unroll
            for (int li = 0; li < B_LD; ++li) {
                int idx = tid + li * THREADS;
                int kr = idx / (BN / 4);
                int nc = (idx % (BN / 4)) * 4;
                const float* v = reinterpret_cast<const float*>(&b_st[li]);
                uint4 hv, lv;
                split_tf32(v[0], hv.x, lv.x);
                split_tf32(v[1], hv.y, lv.y);
                split_tf32(v[2], hv.z, lv.z);
                split_tf32(v[3], hv.w, lv.w);
                *reinterpret_cast<uint4*>(&bH[kr * LDB + nc]) = hv;
                *reinterpret_cast<uint4*>(&bL[kr * LDB + nc]) = lv;
            }
        } else {
#pragma unroll
            for (int li = 0; li < B_LD; ++li) {
                int idx = tid + li * THREADS;
                int nrow = idx / (BK / 4);
                int kc = (idx % (BK / 4)) * 4;
                const float* v = reinterpret_cast<const float*>(&b_st[li]);
#pragma unroll
                for (int j = 0; j < 4; ++j) {
                    uint32_t h, l;
                    split_tf32(v[j], h, l);
                    bH[(kc + j) * LDB + nrow] = h;
                    bL[(kc + j) * LDB + nrow] = l;
                }
            }
        }
    };

    const int ntiles = K / BK;

    load_tiles(0);
    store_tiles(0);
    __syncthreads();

    for (int t = 0; t < ntiles; ++t) {
        const int cur = t & 1;
        const bool has_next = (t + 1) < ntiles;

        if (has_next) load_tiles((t + 1) * BK);

        const uint32_t* aH = AsH + cur * ABUF;
        const uint32_t* aL = AsL + cur * ABUF;
        const uint32_t* bH = BsH + cur * BBUF;
        const uint32_t* bL = BsL + cur * BBUF;
#pragma unroll
        for (int ks = 0; ks < KSTEPS; ++ks) {
            uint32_t ahi[MI][4], alo[MI][4];
#pragma unroll
            for (int mi = 0; mi < MI; ++mi) {
                int r0 = wm + mi * 16 + gr;
                int c0 = ks * 8 + gc;
                ahi[mi][0] = aH[c0 * LDA + r0];
                ahi[mi][1] = aH[c0 * LDA + r0 + 8];
                ahi[mi][2] = aH[(c0 + 4) * LDA + r0];
                ahi[mi][3] = aH[(c0 + 4) * LDA + r0 + 8];
                alo[mi][0] = aL[c0 * LDA + r0];
                alo[mi][1] = aL[c0 * LDA + r0 + 8];
                alo[mi][2] = aL[(c0 + 4) * LDA + r0];
                alo[mi][3] = aL[(c0 + 4) * LDA + r0 + 8];
            }
            uint32_t bhi[NI][2], blo[NI][2];
#pragma unroll
            for (int ni = 0; ni < NI; ++ni) {
                int n0 = wn + ni * 8 + gr;
                int kr = ks * 8 + gc;
                bhi[ni][0] = bH[kr * LDB + n0];
                bhi[ni][1] = bH[(kr + 4) * LDB + n0];
                blo[ni][0] = bL[kr * LDB + n0];
                blo[ni][1] = bL[(kr + 4) * LDB + n0];
            }
#pragma unroll
            for (int mi = 0; mi < MI; ++mi)
#pragma unroll
                for (int ni = 0; ni < NI; ++ni) mma_tf32(acc[mi][ni], ahi[mi], bhi[ni]);
#pragma unroll
            for (int mi = 0; mi < MI; ++mi)
#pragma unroll
                for (int ni = 0; ni < NI; ++ni) mma_tf32(acc[mi][ni], ahi[mi], blo[ni]);
#pragma unroll
            for (int mi = 0; mi < MI; ++mi)
#pragma unroll
                for (int ni = 0; ni < NI; ++ni) mma_tf32(acc[mi][ni], alo[mi], bhi[ni]);
        }

        if (has_next) {
            store_tiles(1 - cur);
            __syncthreads();
        }
    }

#pragma unroll
    for (int mi = 0; mi < MI; ++mi) {
        int r0 = bm + wm + mi * 16 + gr;
#pragma unroll
        for (int ni = 0; ni < NI; ++ni) {
            int c = bn + wn + ni * 8 + gc * 2;
            float2 v0 = make_float2(alpha * acc[mi][ni][0], alpha * acc[mi][ni][1]);
            float2 v1 = make_float2(alpha * acc[mi][ni][2], alpha * acc[mi][ni][3]);
            if (E != nullptr) {
                float2 e0 = *reinterpret_cast<const float2*>(&E[(size_t)r0 * N + c]);
                float2 e1 = *reinterpret_cast<const float2*>(&E[(size_t)(r0 + 8) * N + c]);
                v0.x += beta * e0.x; v0.y += beta * e0.y;
                v1.x += beta * e1.x; v1.y += beta * e1.y;
            }
            *reinterpret_cast<float2*>(&C[(size_t)r0 * N + c]) = v0;
            *reinterpret_cast<float2*>(&C[(size_t)(r0 + 8) * N + c]) = v1;
        }
    }
}

// ---------------- kernels ----------------
template <int BM, int BN, int BK, int WM, int WN, bool TB>
__global__ void __launch_bounds__((BM / WM) * (BN / WN) * 32)
gemm_tc_k(const float* __restrict__ A, const float* __restrict__ B,
          const float* E, float* C, int M, int N, int K, float alpha, float beta)
{
    __shared__ uint32_t AsH[2 * BK * (BM + 8)], AsL[2 * BK * (BM + 8)];
    __shared__ uint32_t BsH[2 * BK * (BN + 8)], BsL[2 * BK * (BN + 8)];
    gemm_tile<BM, BN, BK, WM, WN, TB>(AsH, AsL, BsH, BsL, A, B, E, C,
                                      M, N, K, alpha, beta,
                                      blockIdx.y * BM, blockIdx.x * BN);
}

// Two independent GEMMs fused by grid partition; per-job transpose flags.
template <int BM, int BN, int BK, int WM, int WN, bool TB0, bool TB1>
__global__ void __launch_bounds__((BM / WM) * (BN / WN) * 32)
gemm_pair_k(const float* A0, const float* B0, const float* E0, float* C0,
            int M0, int N0, int K0, float al0, float be0, int gx0, int nb0,
            const float* A1, const float* B1, const float* E1, float* C1,
            int M1, int N1, int K1, float al1, float be1, int gx1)
{
    __shared__ uint32_t AsH[2 * BK * (BM + 8)], AsL[2 * BK * (BM + 8)];
    __shared__ uint32_t BsH[2 * BK * (BN + 8)], BsL[2 * BK * (BN + 8)];
    int b = blockIdx.x;
    if (b < nb0) {
        gemm_tile<BM, BN, BK, WM, WN, TB0>(AsH, AsL, BsH, BsL, A0, B0, E0, C0,
                                           M0, N0, K0, al0, be0,
                                           (b / gx0) * BM, (b % gx0) * BN);
    } else {
        b -= nb0;
        gemm_tile<BM, BN, BK, WM, WN, TB1>(AsH, AsL, BsH, BsL, A1, B1, E1, C1,
                                           M1, N1, K1, al1, be1,
                                           (b / gx1) * BM, (b % gx1) * BN);
    }
}

// ---------------- Newton-Schulz setup kernels ----------------
__global__ void reset_norm_k() { g_ninf_bits = 0u; }

__global__ void rowsum_k(const float* __restrict__ S)
{
    __shared__ float sh[256];
    int r = blockIdx.x;
    float s = 0.0f;
    for (int c = threadIdx.x; c < MM; c += 256) s += fabsf(S[(size_t)r * MM + c]);
    sh[threadIdx.x] = s;
    __syncthreads();
    for (int o = 128; o > 0; o >>= 1) {
        if (threadIdx.x < o) sh[threadIdx.x] += sh[threadIdx.x + o];
        __syncthreads();
    }
    if (threadIdx.x == 0) atomicMax(&g_ninf_bits, __float_as_uint(sh[0]));
}

// Y0 = c*S, X0 = c*I  (c = 1/||S||inf)
__global__ void scale_init_k(const float* __restrict__ S,
                             float* __restrict__ Y0, float* __restrict__ X0)
{
    float c = 1.0f / __uint_as_float(g_ninf_bits);
    int idx = blockIdx.x * blockDim.x + threadIdx.x;
    if (idx < MM * MM) {
        Y0[idx] = c * S[idx];
        int i = idx / MM, j = idx % MM;
        X0[idx] = (i == j) ? c : 0.0f;
    }
}

// ---------------- host helpers (stream-aware) ----------------
template <bool TB>
static void gemm_big(cudaStream_t st, const float* A, const float* B, const float* E,
                     float* C, int M, int N, int K, float alpha, float beta)
{
    dim3 grid(N / 128, M / 128);
    gemm_tc_k<128, 128, 16, 32, 64, TB><<<grid, 256, 0, st>>>(A, B, E, C, M, N, K, alpha, beta);
}

template <bool TB>
static void gemm_mid(cudaStream_t st, const float* A, const float* B, const float* E,
                     float* C, int M, int N, int K, float alpha, float beta)
{
    dim3 grid(N / 64, M / 64);
    gemm_tc_k<64, 64, 16, 32, 32, TB><<<grid, 128, 0, st>>>(A, B, E, C, M, N, K, alpha, beta);
}

template <bool TB0, bool TB1>
static void gemm_pair(cudaStream_t st,
                      const float* A0, const float* B0, const float* E0, float* C0,
                      int M0, int N0, int K0, float al0, float be0,
                      const float* A1, const float* B1, const float* E1, float* C1,
                      int M1, int N1, int K1, float al1, float be1)
{
    int gx0 = N0 / 64, nb0 = gx0 * (M0 / 64);
    int gx1 = N1 / 64, nb1 = gx1 * (M1 / 64);
    gemm_pair_k<64, 64, 16, 32, 32, TB0, TB1><<<nb0 + nb1, 128, 0, st>>>(
        A0, B0, E0, C0, M0, N0, K0, al0, be0, gx0, nb0,
        A1, B1, E1, C1, M1, N1, K1, al1, be1, gx1);
}

extern "C" void kernel_launch(void* const* d_in, const int* in_sizes, int n_in,
                              void* d_out, int out_size)
{
    (void)in_sizes; (void)n_in; (void)out_size;

    const float* state     = (const float*)d_in[0];
    const float* state_cov = (const float*)d_in[1];
    const float* meas      = (const float*)d_in[2];
    const float* control   = (const float*)d_in[3];
    const float* F         = (const float*)d_in[4];
    const float* Q         = (const float*)d_in[5];
    const float* Bc        = (const float*)d_in[6];
    const float* H         = (const float*)d_in[7];
    const float* R         = (const float*)d_in[8];

    float *state_p, *T1, *cov_p, *HP, *S, *PHt, *Ya, *Yb, *Xa, *Xb, *Kg, *innov;
    cudaGetSymbolAddress((void**)&state_p, g_state_p);
    cudaGetSymbolAddress((void**)&T1, g_T1);
    cudaGetSymbolAddress((void**)&cov_p, g_cov_p);
    cudaGetSymbolAddress((void**)&HP, g_HP);
    cudaGetSymbolAddress((void**)&S, g_S);
    cudaGetSymbolAddress((void**)&PHt, g_PHt);
    cudaGetSymbolAddress((void**)&Ya, g_Ya);
    cudaGetSymbolAddress((void**)&Yb, g_Yb);
    cudaGetSymbolAddress((void**)&Xa, g_Xa);
    cudaGetSymbolAddress((void**)&Xb, g_Xb);
    cudaGetSymbolAddress((void**)&Kg, g_K);
    cudaGetSymbolAddress((void**)&innov, g_innov);

    float* out_state = (float*)d_out;                 // [D, B]
    float* out_cov   = out_state + (size_t)DD * BB;   // [D, D]

    // one-time side-stream + events (resource init only; no work is skipped)
    static cudaStream_t s2 = nullptr;
    static cudaEvent_t ev_fork = nullptr, ev_g = nullptr, ev_done = nullptr;
    if (s2 == nullptr) {
        cudaStreamCreateWithFlags(&s2, cudaStreamNonBlocking);
        cudaEventCreateWithFlags(&ev_fork, cudaEventDisableTiming);
        cudaEventCreateWithFlags(&ev_g, cudaEventDisableTiming);
        cudaEventCreateWithFlags(&ev_done, cudaEventDisableTiming);
    }
    cudaStream_t s0 = (cudaStream_t)0;

    // ---- fork ----
    cudaEventRecord(ev_fork, s0);
    cudaStreamWaitEvent(s2, ev_fork, 0);

    // ===== stream s2: state chain (big batch GEMMs) =====
    gemm_big<false>(s2, F, state, nullptr, state_p, DD, BB, DD, 1.0f, 0.0f);
    gemm_big<false>(s2, Bc, control, state_p, state_p, DD, BB, CC, 1.0f, 1.0f);
    gemm_big<false>(s2, H, state_p, meas, innov, MM, BB, DD, -1.0f, 1.0f);

    // ===== stream 0: covariance chain =====
    gemm_mid<false>(s0, F, state_cov, nullptr, T1, DD, DD, DD, 1.0f, 0.0f);
    gemm_mid<true >(s0, T1, F, Q, cov_p, DD, DD, DD, 1.0f, 1.0f);
    gemm_pair<false, true>(s0,
        H,     cov_p, nullptr, HP,  MM, DD, DD, 1.0f, 0.0f,
        cov_p, H,     nullptr, PHt, DD, MM, DD, 1.0f, 0.0f);
    gemm_mid<true>(s0, HP, H, R, S, MM, MM, DD, 1.0f, 1.0f);

    // Newton-Schulz, X-chain form:
    //   Y0 = c*S, X0 = c*I;  per iter: Yn = Y(2I-Y) = 2Y - Y@Y,
    //                                  Xn = X(2I-Y) = 2X - X@Y   (independent)
    //   X -> S^-1;  K = PHt @ X at the end.
    reset_norm_k<<<1, 1, 0, s0>>>();
    rowsum_k<<<MM, 256, 0, s0>>>(S);
    scale_init_k<<<(MM * MM + 255) / 256, 256, 0, s0>>>(S, Ya, Xa);

    float* Y = Ya; float* Yn = Yb;
    float* X = Xa; float* Xn = Xb;
    for (int it = 0; it < NEWTON_ITERS; ++it) {
        gemm_pair<false, false>(s0,
            Y, Y, Y, Yn, MM, MM, MM, -1.0f, 2.0f,
            X, Y, X, Xn, MM, MM, MM, -1.0f, 2.0f);
        float* t = Y; Y = Yn; Yn = t;
        t = X; X = Xn; Xn = t;
    }

    // K = PHt @ X
    gemm_mid<false>(s0, PHt, X, nullptr, Kg, DD, MM, MM, 1.0f, 0.0f);
    cudaEventRecord(ev_g, s0);

    // out_cov on stream 0 (needs K, HP, cov_p)
    gemm_mid<false>(s0, Kg, HP, cov_p, out_cov, DD, DD, MM, -1.0f, 1.0f);

    // out_state on s2 (needs K from stream 0, innov/state_p from s2)
    cudaStreamWaitEvent(s2, ev_g, 0);
    gemm_big<false>(s2, Kg, innov, state_p, out_state, DD, BB, MM, 1.0f, 1.0f);

    // ---- join ----
    cudaEventRecord(ev_done, s2);
    cudaStreamWaitEvent(s0, ev_done, 0);
}